// round 8
// baseline (speedup 1.0000x reference)
#include <cuda_runtime.h>
#include <math_constants.h>

// Global spatial max-pool: [B=64, H=56, W=56, C=256] f32 NHWC -> [B=64, C=256].
//
// R8: exact single-wave grid. 2368 blocks = 148 SMs x 16 CTAs (128 thr,
// occ 16), and 2368 = 64 batches x 37 splits -> every block owns 84-85
// spatial positions of exactly one batch (no straddle), all blocks equal
// size +-1 position, ZERO wave quantization (R2-R7 all had 0.76 or 1.51
// waves; time-weighted occ 89% in R7 == the 1.51-wave tail).
//   - LDG.E.256 streaming loads with L1::no_allocate.L2::evict_first
//     (zero-reuse stream), warp = 1KB coalesced per position.
//   - 4 phases x 32 channel-groups; unroll 4 -> 4KB in flight per warp,
//     64 warps/SM resident.
//   - epilogue: 4-phase smem reduce, partial write, release fence + batch
//     counter; last of 37 blocks per batch does the final reduce with an
//     acquire fence (R7 correctness fix kept). Counters self-reset for
//     graph replay; max is order-independent.

#define B_DIM   64
#define HW      3136
#define C_DIM   256
#define BPB     37                 // blocks per batch
#define GRID    (B_DIM * BPB)      // 2368 = 148 * 16
#define PHASES  4

__device__ float2       g_partial[GRID * (C_DIM / 2)];  // [b][slot][128] = 2.4 MB
__device__ unsigned int g_count[B_DIM];                  // zero-init, self-resetting

__global__ __launch_bounds__(128, 16)
void gmax_wave(const float* __restrict__ in, float* __restrict__ out) {
    const int blk  = blockIdx.x;           // 0..2367
    const int b    = blk / BPB;
    const int slot = blk - b * BPB;        // 0..36
    const int t    = threadIdx.x;
    const int g    = t & 31;               // 8-channel group (32 bytes)
    const int p    = t >> 5;               // spatial phase 0..3

    // Equal-split positions of batch b: [slot*HW/37, (slot+1)*HW/37)
    const int start = b * HW + (slot * HW) / BPB;
    const int end   = b * HW + ((slot + 1) * HW) / BPB;

    float a0 = -CUDART_INF_F, a1 = -CUDART_INF_F, a2 = -CUDART_INF_F, a3 = -CUDART_INF_F;
    float a4 = -CUDART_INF_F, a5 = -CUDART_INF_F, a6 = -CUDART_INF_F, a7 = -CUDART_INF_F;

    #pragma unroll 4
    for (int pos = start + p; pos < end; pos += PHASES) {
        const float* addr = in + ((size_t)pos << 8) + (g << 3);
        float v0, v1, v2, v3, v4, v5, v6, v7;
        asm volatile(
            "ld.global.nc.L1::no_allocate.L2::evict_first.v8.f32 "
            "{%0,%1,%2,%3,%4,%5,%6,%7}, [%8];"
            : "=f"(v0), "=f"(v1), "=f"(v2), "=f"(v3),
              "=f"(v4), "=f"(v5), "=f"(v6), "=f"(v7)
            : "l"(addr));
        a0 = fmaxf(a0, v0);  a1 = fmaxf(a1, v1);
        a2 = fmaxf(a2, v2);  a3 = fmaxf(a3, v3);
        a4 = fmaxf(a4, v4);  a5 = fmaxf(a5, v5);
        a6 = fmaxf(a6, v6);  a7 = fmaxf(a7, v7);
    }

    // Cross-phase reduce: sm[p][c2], c2 = float2 channel slot 0..127.
    __shared__ float2 sm[PHASES][C_DIM / 2];
    sm[p][4 * g + 0] = make_float2(a0, a1);
    sm[p][4 * g + 1] = make_float2(a2, a3);
    sm[p][4 * g + 2] = make_float2(a4, a5);
    sm[p][4 * g + 3] = make_float2(a6, a7);
    __syncthreads();

    {   // thread t owns channels (2t, 2t+1)
        float2 m = sm[0][t];
        #pragma unroll
        for (int ph = 1; ph < PHASES; ++ph) {
            float2 v = sm[ph][t];
            m.x = fmaxf(m.x, v.x);
            m.y = fmaxf(m.y, v.y);
        }
        g_partial[blk * (C_DIM / 2) + t] = m;
    }

    // Release: partial visible before counter bump.
    __threadfence();
    __shared__ bool amLast;
    if (t == 0) {
        unsigned int old = atomicAdd(&g_count[b], 1u);
        amLast = (old == BPB - 1);
    }
    __syncthreads();

    if (amLast) {
        __threadfence();   // acquire: order partial reads after counter
        const float2* part = g_partial + b * BPB * (C_DIM / 2);
        float2 m = part[t];
        #pragma unroll
        for (int s = 1; s < BPB; ++s) {
            float2 v = part[s * (C_DIM / 2) + t];
            m.x = fmaxf(m.x, v.x);
            m.y = fmaxf(m.y, v.y);
        }
        reinterpret_cast<float2*>(out)[b * (C_DIM / 2) + t] = m;
        if (t == 0) g_count[b] = 0;   // self-reset for graph replay
    }
}

extern "C" void kernel_launch(void* const* d_in, const int* in_sizes, int n_in,
                              void* d_out, int out_size) {
    const float* in  = (const float*)d_in[0];
    float*       out = (float*)d_out;
    gmax_wave<<<GRID, 128>>>(in, out);
}

// round 9
// speedup vs baseline: 1.0919x; 1.0919x over previous
#include <cuda_runtime.h>
#include <math_constants.h>

// Global spatial max-pool: [B=64, H=56, W=56, C=256] f32 NHWC -> [B=64, C=256].
//
// R9: plateau-confirmation probe. Eight rounds of evidence say ~6 TB/s
// (75% of spec) is this chip's effective read-stream ceiling: DRAM% is flat
// at 73-76% for every config with >600 resident blocks, independent of
// occupancy (70-97%), MLP (2-28), epilogue structure, or wave phase.
// This round holds the proven R7 streaming shape constant (compile-time
// trip counts, immediate LDG.E.256 offsets, evict-first policy, 1.51 waves,
// 64 warps/SM) and changes ONLY block granularity: 512-thr blocks, SPLIT=14
// -> 896 blocks, quartering epilogue/atomic count.
//   - 16 phases x 32 channel-groups; ITERS = 224/16 = 14, unroll 4.
//   - smem cross-phase reduce (16-way), conflict-free.
//   - fused final reduce: last block per batch, release fence on write side,
//     acquire fence on read side (R7 correctness fix), counters self-reset
//     for graph replay.

#define B_DIM   64
#define HW      3136              // 56*56
#define C_DIM   256
#define SPLIT   14
#define SPAN    (HW / SPLIT)      // 224 positions per block
#define PHASES  16
#define ITERS   (SPAN / PHASES)   // 14
#define NBLK    (B_DIM * SPLIT)   // 896

__device__ float        g_partial[NBLK * C_DIM];   // 896 KB scratch
__device__ unsigned int g_count[B_DIM];            // zero-init, self-resetting

__global__ __launch_bounds__(512, 4)
void gmax_fused(const float* __restrict__ in, float* __restrict__ out) {
    const int blk   = blockIdx.x;            // 0..895
    const int b     = blk / SPLIT;
    const int split = blk - b * SPLIT;
    const int t     = threadIdx.x;
    const int g     = t & 31;                // 8-channel group (32 bytes)
    const int p     = t >> 5;                // spatial phase 0..15

    const float* __restrict__ base =
        in + (((size_t)(b * HW + split * SPAN + p)) << 8) + (g << 3);

    float a0 = -CUDART_INF_F, a1 = -CUDART_INF_F, a2 = -CUDART_INF_F, a3 = -CUDART_INF_F;
    float a4 = -CUDART_INF_F, a5 = -CUDART_INF_F, a6 = -CUDART_INF_F, a7 = -CUDART_INF_F;

    #pragma unroll 4
    for (int i = 0; i < ITERS; ++i) {
        float v0, v1, v2, v3, v4, v5, v6, v7;
        asm volatile(
            "ld.global.nc.L1::no_allocate.L2::evict_first.v8.f32 "
            "{%0,%1,%2,%3,%4,%5,%6,%7}, [%8];"
            : "=f"(v0), "=f"(v1), "=f"(v2), "=f"(v3),
              "=f"(v4), "=f"(v5), "=f"(v6), "=f"(v7)
            : "l"(base + (size_t)i * (PHASES * C_DIM)));
        a0 = fmaxf(a0, v0);  a1 = fmaxf(a1, v1);
        a2 = fmaxf(a2, v2);  a3 = fmaxf(a3, v3);
        a4 = fmaxf(a4, v4);  a5 = fmaxf(a5, v5);
        a6 = fmaxf(a6, v6);  a7 = fmaxf(a7, v7);
    }

    // Cross-phase reduce through smem: sm[p*256 + c], conflict-free.
    __shared__ float sm[PHASES * C_DIM];
    float* my = sm + t * 8;  // == p*256 + g*8
    my[0] = a0; my[1] = a1; my[2] = a2; my[3] = a3;
    my[4] = a4; my[5] = a5; my[6] = a6; my[7] = a7;
    __syncthreads();

    // Threads 0..255: thread t == channel c, reduce over 16 phases.
    if (t < C_DIM) {
        float m = sm[t];
        #pragma unroll
        for (int ph = 1; ph < PHASES; ++ph)
            m = fmaxf(m, sm[ph * C_DIM + t]);
        g_partial[blk * C_DIM + t] = m;
    }

    // Release: partial visible before counter bump.
    __threadfence();
    __shared__ bool amLast;
    if (t == 0) {
        unsigned int old = atomicAdd(&g_count[b], 1u);
        amLast = (old == SPLIT - 1);
    }
    __syncthreads();

    if (amLast && t < C_DIM) {
        __threadfence();   // acquire: order partial reads after counter
        const float* part = g_partial + b * SPLIT * C_DIM;
        float m = part[t];
        #pragma unroll
        for (int s = 1; s < SPLIT; ++s)
            m = fmaxf(m, part[s * C_DIM + t]);
        out[b * C_DIM + t] = m;
        if (t == 0) g_count[b] = 0;   // self-reset for next graph replay
    }
}

extern "C" void kernel_launch(void* const* d_in, const int* in_sizes, int n_in,
                              void* d_out, int out_size) {
    const float* in  = (const float*)d_in[0];
    float*       out = (float*)d_out;
    gmax_fused<<<NBLK, 512>>>(in, out);
}